// round 13
// baseline (speedup 1.0000x reference)
#include <cuda_runtime.h>

// out[i, j] = (2*x[i, j] + 3) / (i + 1), x is 8192x8192 fp32.
//
// FINAL: HBM-bound streaming at ~7.2 TB/s effective (~90% of 8 TB/s HBM3e
// spec) — the measured roofline for a zero-reuse 512 MiB read+write stream
// on GB300. 13-config sweep, all levers measured:
//   block size (ncu us):  64T:75.4  128T:73.4-75.2  256T:74.3-74.9  512T:78.7
//   per-thread MLP:       U1:80.2   U2:75.7   U4:73.4-75.2   U8:74.2
//   persistent 740-CTA grid: 85.8 (load-imbalance tail — HW waves win)
//   LDG.256 (Blackwell v8.f32): 74.8 (neutral — LSU not binding)
//   64-bit idx, occ 48-82%, 22-46 regs: all neutral on DRAM ceiling
// DRAM bus is the binding resource; compute pipes <7%.
//
// Config: THREADS=128, UNROLL=4 (512 vecs/CTA — the L1tex batch U-curve
// minimum), flat 32768-CTA grid (exact, no tail), front-batched LDG.128
// (4 in flight/thread), streaming (.cs) hints, 32-bit indexing, one
// MUFU.RCP per float4 (divisor uniform per row; 8192 % 4 == 0 so all 4
// lanes of a float4 share a row).

static constexpr int N_ROWS = 8192;
static constexpr int N_COLS = 8192;
static constexpr int N_VEC = (N_ROWS / 4) * N_COLS;     // 2^24 float4s (fits int)
static constexpr int THREADS = 128;
static constexpr int UNROLL = 4;
// 2^24 / (128*4) = 32768 blocks, exact — no tail.
static constexpr int BLOCKS = N_VEC / (THREADS * UNROLL);

__global__ void __launch_bounds__(THREADS)
affine_rowdiv_kernel(const float4* __restrict__ in, float4* __restrict__ out) {
    int base = blockIdx.x * (THREADS * UNROLL) + threadIdx.x;

    // Front-batch 4 independent LDG.128 per thread.
    float4 v[UNROLL];
#pragma unroll
    for (int k = 0; k < UNROLL; k++) {
        v[k] = __ldcs(&in[base + k * THREADS]);
    }

#pragma unroll
    for (int k = 0; k < UNROLL; k++) {
        int idx = base + k * THREADS;
        // 2048 float4s per row -> row = idx >> 11
        int row = idx >> 11;
        float inv = 1.0f / (float)(row + 1);
        float4 r;
        r.x = fmaf(2.0f, v[k].x, 3.0f) * inv;
        r.y = fmaf(2.0f, v[k].y, 3.0f) * inv;
        r.z = fmaf(2.0f, v[k].z, 3.0f) * inv;
        r.w = fmaf(2.0f, v[k].w, 3.0f) * inv;
        __stcs(&out[idx], r);
    }
}

extern "C" void kernel_launch(void* const* d_in, const int* in_sizes, int n_in,
                              void* d_out, int out_size) {
    const float4* in = (const float4*)d_in[0];
    float4* out = (float4*)d_out;
    affine_rowdiv_kernel<<<BLOCKS, THREADS>>>(in, out);
}